// round 13
// baseline (speedup 1.0000x reference)
#include <cuda_runtime.h>
#include <cuda_fp16.h>
#include <cstdint>

#define N_GENES 20000
#define UNITS   10000
#define DEG     32
#define BATCH   128
#define GRID    625      // MUST be <= resident capacity (5/SM x 148 = 740)

// |feature| transposed to [gene][batch] in fp16: 5.12 MB, L2-resident.
// Row = 256B; each (unit, deg) gather reads one full row, coalesced.
// Gather is at the L2 slice-service cap (invariant 10.8-11.2us, R4-R12).
__device__ __half g_featT[(size_t)N_GENES * BATCH];

// Device-barrier state. Self-resetting each launch (last CTA zeroes both),
// so the kernel is deterministic across graph replays.
__device__ unsigned g_arrive = 0;
__device__ unsigned g_done   = 0;

// ---------------------------------------------------------------------------
// Fused kernel: phase 1 transposes 32 genes/CTA into g_featT; device-wide
// barrier (all 625 CTAs co-resident by __launch_bounds__(256,5)); phase 2
// gathers 16 units/CTA with the proven best loop (each LDG.128 covers two
// gene rows; 4 loads batched; half2 accumulate, fp32 flush every 8 genes).
// ---------------------------------------------------------------------------
__global__ void __launch_bounds__(256, 5) ppi_fused_kernel(
    const float* __restrict__ feature,
    const int*   __restrict__ ppi,     // int32 (JAX x64-disabled)
    const float* __restrict__ kern,
    const float* __restrict__ bias,
    float*       __restrict__ out)
{
    __shared__ __align__(16) float tile[BATCH][33];   // 16.9 KB (overlaid below)
    const int tid = threadIdx.x;

    // ---- Phase 1: transpose + fabs + fp16, 32 genes ----
    const int gx = blockIdx.x * 32;
    {
        const int tx  = tid & 31;
        const int row = tid >> 5;
#pragma unroll
        for (int k = 0; k < BATCH; k += 8)
            tile[row + k][tx] = fabsf(feature[(size_t)(row + k) * N_GENES + (gx + tx)]);
        __syncthreads();
        // 64 consecutive threads emit one contiguous 256B gene row.
#pragma unroll
        for (int tt = 0; tt < 8; tt++) {
            const int task = tt * 256 + tid;
            const int g_l  = task >> 6;
            const int p    = task & 63;
            const __half2 h = __floats2half2_rn(tile[2 * p][g_l], tile[2 * p + 1][g_l]);
            *(__half2*)&g_featT[(size_t)(gx + g_l) * BATCH + 2 * p] = h;
        }
    }

    // ---- Device-wide barrier (release: fence+atomic; acquire: spin+fence) ----
    __syncthreads();                       // all threads' featT stores precede arrival
    if (tid == 0) {
        __threadfence();
        atomicAdd(&g_arrive, 1u);
        while (*(volatile unsigned*)&g_arrive < GRID) __nanosleep(128);
        __threadfence();
    }
    __syncthreads();

    // ---- Phase 2: gather 16 units (2 rounds of 8, one warp per unit) ----
    const int lane   = tid & 31;
    const int hlane  = lane & 15;          // 16B batch-slice owner
    const int hsel   = lane >> 4;          // 0: even gene, 1: odd gene
    const int warp   = tid >> 5;
    const int u_base = blockIdx.x * 16;
    const char* base = (const char*)g_featT + hlane * 16;

    float (*otile)[BATCH + 4] = (float (*)[BATCH + 4])&tile[0][0];  // 8.4 KB overlay

#pragma unroll
    for (int j = 0; j < 2; j++) {
        const int u     = u_base + j * 8 + warp;
        const int myoff = ppi[(size_t)u * DEG + lane] << 8;   // 256B row offset
        const float kv  = kern[u];
        const float bv  = bias[u];

        float facc[8];
#pragma unroll
        for (int i = 0; i < 8; i++) facc[i] = 0.f;

#pragma unroll
        for (int half = 0; half < 2; half++) {     // 2 flush periods x 16 genes
            __half2 hacc[4];
#pragma unroll
            for (int i = 0; i < 4; i++) hacc[i] = __floats2half2_rn(0.f, 0.f);

#pragma unroll
            for (int bb = 0; bb < 2; bb++) {       // 2 batches of 4 LDG.128
                uint4 raw[4];
#pragma unroll
                for (int q = 0; q < 4; q++) {
                    const int it  = half * 8 + bb * 4 + q;          // 0..15
                    const int off = __shfl_sync(0xffffffffu, myoff, 2 * it + hsel);
                    raw[q] = *(const uint4*)(base + off);
                }
#pragma unroll
                for (int q = 0; q < 4; q++) {
                    hacc[0] = __hadd2(hacc[0], *(const __half2*)&raw[q].x);
                    hacc[1] = __hadd2(hacc[1], *(const __half2*)&raw[q].y);
                    hacc[2] = __hadd2(hacc[2], *(const __half2*)&raw[q].z);
                    hacc[3] = __hadd2(hacc[3], *(const __half2*)&raw[q].w);
                }
            }
#pragma unroll
            for (int i = 0; i < 4; i++) {          // fp32 flush
                const float2 f = __half22float2(hacc[i]);
                facc[2 * i]     += f.x;
                facc[2 * i + 1] += f.y;
            }
        }

        // Combine the two half-warps (disjoint gene subsets, same batch slice).
#pragma unroll
        for (int i = 0; i < 8; i++)
            facc[i] += __shfl_xor_sync(0xffffffffu, facc[i], 16);

        if (lane < 16) {
            float r[8];
#pragma unroll
            for (int i = 0; i < 8; i++)
                r[i] = tanhf(fmaf(facc[i], kv, bv));
            *(float4*)&otile[j * 8 + warp][hlane * 8]     = make_float4(r[0], r[1], r[2], r[3]);
            *(float4*)&otile[j * 8 + warp][hlane * 8 + 4] = make_float4(r[4], r[5], r[6], r[7]);
        }
    }
    __syncthreads();

    // Coalesced streaming output: 16-thread groups write contiguous 64B
    // chunks of one batch row (write-once; keep out of the hot L2 set).
    for (int t = tid; t < BATCH * 16; t += 256) {
        const int u_l = t & 15;
        const int b   = t >> 4;
        __stcs(&out[(size_t)b * UNITS + (u_base + u_l)], otile[u_l][b]);
    }

    // ---- Self-reset for the next (graph-replayed) launch ----
    if (tid == 0) {
        const unsigned d = atomicAdd(&g_done, 1u);
        if (d == GRID - 1) {               // last CTA: everyone passed barrier
            g_arrive = 0u;
            g_done   = 0u;
            __threadfence();
        }
    }
}

// ---------------------------------------------------------------------------
extern "C" void kernel_launch(void* const* d_in, const int* in_sizes, int n_in,
                              void* d_out, int out_size) {
    const float* feature = (const float*)d_in[0];
    const int*   ppi     = (const int*)d_in[1];
    const float* kern    = (const float*)d_in[2];
    const float* bias    = (const float*)d_in[3];
    float*       out     = (float*)d_out;

    ppi_fused_kernel<<<GRID, 256>>>(feature, ppi, kern, bias, out);
}

// round 14
// speedup vs baseline: 1.1234x; 1.1234x over previous
#include <cuda_runtime.h>
#include <cuda_fp16.h>
#include <cstdint>

#define N_GENES 20000
#define UNITS   10000
#define DEG     32
#define BATCH   128

// |feature| transposed to [gene][batch] in fp16: 5.12 MB, L2-resident.
// Row = 256B; each (unit, deg) gather reads one full row, coalesced.
// The gather sits at the L2 slice-service floor (10.8-11.2us node,
// invariant across R4-R13 restructurings). Bytes irreducible at fp16.
__device__ __half g_featT[(size_t)N_GENES * BATCH];

// ---------------------------------------------------------------------------
// K1: transpose + fabs + fp16.  feature [128, 20000] -> featT [N, B].
// One CTA per 32-gene column block covering the FULL batch: each gene's
// 256B featT row is written contiguously by one 64-thread group.
// ---------------------------------------------------------------------------
__global__ void __launch_bounds__(256) transpose_abs_kernel(
    const float* __restrict__ feature)
{
    __shared__ float tile[BATCH][33];            // tile[batch][gene], 16.9 KB
    const int gx  = blockIdx.x * 32;
    const int tx  = threadIdx.x & 31;            // gene within block
    const int row = threadIdx.x >> 5;            // batch row 0..7

#pragma unroll
    for (int k = 0; k < BATCH; k += 8)
        tile[row + k][tx] = fabsf(feature[(size_t)(row + k) * N_GENES + (gx + tx)]);
    __syncthreads();

    // 64 consecutive threads emit one contiguous 256B gene row.
#pragma unroll
    for (int tt = 0; tt < 8; tt++) {
        const int task = tt * 256 + threadIdx.x;
        const int g_l  = task >> 6;              // 0..31
        const int p    = task & 63;              // batch pair
        const __half2 h = __floats2half2_rn(tile[2 * p][g_l], tile[2 * p + 1][g_l]);
        *(__half2*)&g_featT[(size_t)(gx + g_l) * BATCH + 2 * p] = h;
    }
}

// ---------------------------------------------------------------------------
// K2: gather-sum (best-measured config). One warp per unit; each LDG.128
// covers two gene rows (half-warp per gene, 16B batch slice per lane);
// batches of 4 LDG.128 in flight. half2 accumulate, fp32 flush every 8
// genes; cross-half shfl_xor(16); STG.128 streaming epilogue.
// ---------------------------------------------------------------------------
__global__ void __launch_bounds__(256, 5) ppi_gather_kernel(
    const int*   __restrict__ ppi,     // int32 (JAX x64-disabled)
    const float* __restrict__ kern,
    const float* __restrict__ bias,
    float*       __restrict__ out)
{
    __shared__ float tile[8][BATCH + 4];

    const int lane   = threadIdx.x & 31;
    const int hlane  = lane & 15;                 // batch-slice owner (16B)
    const int hsel   = lane >> 4;                 // 0: even gene, 1: odd gene
    const int warp   = threadIdx.x >> 5;
    const int u_base = blockIdx.x * 8;
    const int u      = u_base + warp;

    // Preamble: row byte-offset of ppi[u][lane] (row = 256B) + unit params.
    const int myoff = ppi[(size_t)u * DEG + lane] << 8;
    const float kv  = kern[u];
    const float bv  = bias[u];
    const char* base = (const char*)g_featT + hlane * 16;

    float facc[8];
#pragma unroll
    for (int j = 0; j < 8; j++) facc[j] = 0.f;

#pragma unroll
    for (int half = 0; half < 2; half++) {        // 2 flush periods x 16 genes
        __half2 hacc[4];
#pragma unroll
        for (int j = 0; j < 4; j++) hacc[j] = __floats2half2_rn(0.f, 0.f);

#pragma unroll
        for (int bb = 0; bb < 2; bb++) {          // 2 batches of 4 LDG.128
            uint4 raw[4];
#pragma unroll
            for (int q = 0; q < 4; q++) {
                const int it  = half * 8 + bb * 4 + q;          // 0..15
                const int off = __shfl_sync(0xffffffffu, myoff, 2 * it + hsel);
                raw[q] = *(const uint4*)(base + off);
            }
#pragma unroll
            for (int q = 0; q < 4; q++) {
                hacc[0] = __hadd2(hacc[0], *(const __half2*)&raw[q].x);
                hacc[1] = __hadd2(hacc[1], *(const __half2*)&raw[q].y);
                hacc[2] = __hadd2(hacc[2], *(const __half2*)&raw[q].z);
                hacc[3] = __hadd2(hacc[3], *(const __half2*)&raw[q].w);
            }
        }
#pragma unroll
        for (int j = 0; j < 4; j++) {             // fp32 flush
            const float2 f = __half22float2(hacc[j]);
            facc[2 * j]     += f.x;
            facc[2 * j + 1] += f.y;
        }
    }

    // Combine the two half-warps (same batch slice, disjoint gene subsets).
#pragma unroll
    for (int j = 0; j < 8; j++)
        facc[j] += __shfl_xor_sync(0xffffffffu, facc[j], 16);

    if (lane < 16) {                              // conflict-free 512B row
        float r[8];
#pragma unroll
        for (int j = 0; j < 8; j++)
            r[j] = tanhf(fmaf(facc[j], kv, bv));
        *(float4*)&tile[warp][hlane * 8]     = make_float4(r[0], r[1], r[2], r[3]);
        *(float4*)&tile[warp][hlane * 8 + 4] = make_float4(r[4], r[5], r[6], r[7]);
    }
    __syncthreads();

    // STG.128 streaming epilogue: thread t packs units [4q, 4q+4) of batch
    // row b into one float4. smem reads conflict-free (bank = (16q+4j+b)%32
    // spans all 32 banks across the warp); stores 16B-aligned (u_base%8==0).
    {
        const int t = threadIdx.x;                // 256 threads, 256 tasks
        const int b = t >> 1;
        const int q = t & 1;
        const float4 v = make_float4(tile[q * 4 + 0][b], tile[q * 4 + 1][b],
                                     tile[q * 4 + 2][b], tile[q * 4 + 3][b]);
        __stcs((float4*)&out[(size_t)b * UNITS + u_base + q * 4], v);
    }
}

// ---------------------------------------------------------------------------
extern "C" void kernel_launch(void* const* d_in, const int* in_sizes, int n_in,
                              void* d_out, int out_size) {
    const float* feature = (const float*)d_in[0];
    const int*   ppi     = (const int*)d_in[1];
    const float* kern    = (const float*)d_in[2];
    const float* bias    = (const float*)d_in[3];
    float*       out     = (float*)d_out;

    transpose_abs_kernel<<<N_GENES / 32, 256>>>(feature);        // 625 CTAs
    ppi_gather_kernel<<<UNITS / 8, 256>>>(ppi, kern, bias, out); // 1250 CTAs
}